// round 15
// baseline (speedup 1.0000x reference)
#include <cuda_runtime.h>
#include <cuda_fp16.h>
#include <cstdint>
#include <math.h>

// Problem dims
#define B_ 512
#define S_ 128
#define D_ 256
#define H_ 4
#define DH_ 64
#define FF_ 384
#define L_ 6
#define ROWS_ (B_ * S_)
#define SCALE_ 0.125f
#define LOG2E_ 1.4426950408889634f

#define DD_   (D_ * D_)
#define D3D_  (3 * D_ * D_)
#define FFD_  (FF_ * D_)
#define DFF_  (D_ * FF_)
#define OFF_PIW 0
#define OFF_POW (L_ * D3D_)
#define OFF_L1W (OFF_POW + L_ * DD_)
#define OFF_L2W (OFF_L1W + L_ * FFD_)
#define W_TOTAL (OFF_L2W + L_ * DFF_)

// ---------------- scratch (device globals) ----------------------------------
__device__ float g_h    [(size_t)ROWS_ * D_];
__device__ float g_stats[(size_t)ROWS_ * 2];     // (mean, rstd) per row
__device__ __half g_qkvH[(size_t)ROWS_ * 3 * D_];
__device__ __half g_hnH [(size_t)ROWS_ * D_];
__device__ __half g_tmpH[(size_t)ROWS_ * FF_];
__device__ __half g_wH  [W_TOTAL];

extern __shared__ char dyn_smem[];

// ======================= helpers ===========================================
__device__ __forceinline__ uint32_t smem_u32(const void* p) {
    uint32_t a;
    asm("{ .reg .u64 t; cvta.to.shared.u64 t, %1; cvt.u32.u64 %0, t; }"
        : "=r"(a) : "l"(p));
    return a;
}
__device__ __forceinline__ void ldsm4(uint32_t a, uint32_t* r) {
    asm volatile("ldmatrix.sync.aligned.m8n8.x4.shared.b16 {%0,%1,%2,%3}, [%4];"
                 : "=r"(r[0]), "=r"(r[1]), "=r"(r[2]), "=r"(r[3]) : "r"(a));
}
__device__ __forceinline__ void ldsm2(uint32_t a, uint32_t* r) {
    asm volatile("ldmatrix.sync.aligned.m8n8.x2.shared.b16 {%0,%1}, [%2];"
                 : "=r"(r[0]), "=r"(r[1]) : "r"(a));
}
__device__ __forceinline__ void ldsm2t(uint32_t a, uint32_t* r) {
    asm volatile("ldmatrix.sync.aligned.m8n8.x2.trans.shared.b16 {%0,%1}, [%2];"
                 : "=r"(r[0]), "=r"(r[1]) : "r"(a));
}
__device__ __forceinline__ void mma16816h(float* d, const uint32_t* a,
                                          const uint32_t* b) {
    asm volatile("mma.sync.aligned.m16n8k16.row.col.f32.f16.f16.f32 "
                 "{%0,%1,%2,%3}, {%4,%5,%6,%7}, {%8,%9}, {%0,%1,%2,%3};"
                 : "+f"(d[0]), "+f"(d[1]), "+f"(d[2]), "+f"(d[3])
                 : "r"(a[0]), "r"(a[1]), "r"(a[2]), "r"(a[3]),
                   "r"(b[0]), "r"(b[1]));
}
__device__ __forceinline__ uint32_t pack2h(float a, float b) {
    __half2 h = __floats2half2_rn(a, b);
    uint32_t r;
    memcpy(&r, &h, 4);
    return r;
}
__device__ __forceinline__ void cp_async16(uint32_t sa, const void* ga) {
    asm volatile("cp.async.cg.shared.global [%0], [%1], 16;"
                 :: "r"(sa), "l"(ga) : "memory");
}
#define CP_COMMIT() asm volatile("cp.async.commit_group;" ::: "memory")
#define CP_WAIT(N)  asm volatile("cp.async.wait_group %0;" :: "n"(N) : "memory")

// ---------------- weight preconversion (fp32 -> fp16) ------------------------
__global__ __launch_bounds__(256) void wconv_kernel(
    const float* __restrict__ src, __half* __restrict__ dst, int n8)
{
    int idx = blockIdx.x * 256 + threadIdx.x;
    if (idx >= n8) return;
    const float* p = src + (size_t)idx * 8;
    float4 v0 = *(const float4*)(p);
    float4 v1 = *(const float4*)(p + 4);
    uint4 o;
    o.x = pack2h(v0.x, v0.y);
    o.y = pack2h(v0.z, v0.w);
    o.z = pack2h(v1.x, v1.y);
    o.w = pack2h(v1.z, v1.w);
    *(uint4*)(dst + (size_t)idx * 8) = o;
}

// ======================= fp16 mma GEMM ======================================
// 3-stage cp.async pipeline; RES recomputes LN residual from h + stats.
#define GO_BIAS  0u
#define GO_NW    512u
#define GO_NB    1024u
#define GO_STAGE 2048u
#define STAGE_SZ 32768u
#define G_SMEM   (2048 + 3 * 32768)   // 100352

__device__ __forceinline__ void gemm_issue_chunk(
    uint32_t sb, const __half* A, const __half* W,
    int bm, int bn, int K, int c, int s_row, int s_g, uint32_t s_off)
{
    const int kc = c << 6;
    const uint32_t stage = GO_STAGE + (uint32_t)(c % 3) * STAGE_SZ;
#pragma unroll
    for (int it = 0; it < 4; it++) {
        uint32_t off = s_off + (uint32_t)(it * 32 * 128);
        int row = s_row + it * 32;
        cp_async16(sb + stage + off,
                   A + (size_t)(bm + row) * K + kc + s_g * 8);
        cp_async16(sb + stage + 16384 + off,
                   W + (size_t)(bn + row) * K + kc + s_g * 8);
    }
    CP_COMMIT();
}

template<bool GELU, bool RES, bool HASB, bool OUTH>
__global__ __launch_bounds__(256)
void mgemm_kernel(const __half* __restrict__ A, const __half* __restrict__ W,
                  const float* __restrict__ bias,
                  const float* __restrict__ hsrc,   // fp32 h (residual source)
                  const float* __restrict__ stats,  // per-row (mean, rstd)
                  const float* __restrict__ nw, const float* __restrict__ nb,
                  float* __restrict__ Cf, __half* __restrict__ Ch,
                  int M, int N, int K)
{
    char* smem = dyn_smem;
    const uint32_t sb = smem_u32(smem);
    const int tid  = threadIdx.x;
    const int lane = tid & 31;
    const int warp = tid >> 5;
    const int bm = blockIdx.y << 7;
    const int bn = blockIdx.x << 7;
    const int wm = (warp >> 2) << 6;
    const int wn = (warp & 3) << 5;

    float* sbias = (float*)(smem + GO_BIAS);
    float* snw   = (float*)(smem + GO_NW);
    float* snb   = (float*)(smem + GO_NB);
    if (HASB && tid < 128) sbias[tid] = bias[bn + tid];
    if (RES && tid < 128) {
        snw[tid] = nw[bn + tid];
        snb[tid] = nb[bn + tid];
    }

    float acc[4][4][4];
#pragma unroll
    for (int i = 0; i < 4; i++)
#pragma unroll
        for (int j = 0; j < 4; j++)
#pragma unroll
            for (int k = 0; k < 4; k++) acc[i][j][k] = 0.0f;

    const int a_row = lane & 15;
    const int a_cg  = lane >> 4;
    const int bq_sub = (lane >> 4) & 1;
    const int bq_cg  = (lane >> 3) & 1;
    const int bq_row = lane & 7;

    const int s_row = tid >> 3;
    const int s_g   = tid & 7;
    const uint32_t s_off =
        (uint32_t)(s_row * 128 + ((s_g ^ (s_row & 7)) << 4));

    const int nch = K >> 6;

    gemm_issue_chunk(sb, A, W, bm, bn, K, 0, s_row, s_g, s_off);
    gemm_issue_chunk(sb, A, W, bm, bn, K, 1, s_row, s_g, s_off);
    for (int c = 0; c < nch; c++) {
        if (c + 1 < nch) { CP_WAIT(1); } else { CP_WAIT(0); }
        __syncthreads();   // chunk c visible; stage (c+2)%3 free (chunk c-1 consumed)
        if (c + 2 < nch)
            gemm_issue_chunk(sb, A, W, bm, bn, K, c + 2, s_row, s_g, s_off);

        const uint32_t sA = sb + GO_STAGE + (uint32_t)(c % 3) * STAGE_SZ;
        const uint32_t sW = sA + 16384;
#pragma unroll
        for (int ks = 0; ks < 4; ks++) {
            uint32_t ah[4][4], wh[2][4];
#pragma unroll
            for (int mt = 0; mt < 4; mt++) {
                int row = wm + mt * 16 + a_row;
                int cg  = ks * 2 + a_cg;
                ldsm4(sA + row * 128 + ((cg ^ (row & 7)) << 4), ah[mt]);
            }
#pragma unroll
            for (int j = 0; j < 2; j++) {
                int row = wn + (2 * j + bq_sub) * 8 + bq_row;
                int cg  = ks * 2 + bq_cg;
                ldsm4(sW + row * 128 + ((cg ^ (row & 7)) << 4), wh[j]);
            }
#pragma unroll
            for (int mt = 0; mt < 4; mt++)
#pragma unroll
                for (int j = 0; j < 2; j++) {
                    mma16816h(acc[mt][2 * j],     ah[mt], &wh[j][0]);
                    mma16816h(acc[mt][2 * j + 1], ah[mt], &wh[j][2]);
                }
        }
    }

    // ---- epilogue ----
#pragma unroll
    for (int mt = 0; mt < 4; mt++) {
        int r = bm + wm + mt * 16 + (lane >> 2);
        float2 st0, st1;
        if (RES) {
            st0 = *(const float2*)(stats + 2 * r);
            st1 = *(const float2*)(stats + 2 * (r + 8));
        }
#pragma unroll
        for (int nt = 0; nt < 4; nt++) {
            int cl = wn + nt * 8 + ((lane & 3) << 1);
            int c  = bn + cl;
            float2 v0 = make_float2(acc[mt][nt][0], acc[mt][nt][1]);
            float2 v1 = make_float2(acc[mt][nt][2], acc[mt][nt][3]);
            if (HASB) {
                float b0 = sbias[cl], b1 = sbias[cl + 1];
                v0.x += b0; v0.y += b1; v1.x += b0; v1.y += b1;
            }
            if (GELU) {
                v0.x = 0.5f * v0.x * (1.0f + erff(v0.x * 0.70710678f));
                v0.y = 0.5f * v0.y * (1.0f + erff(v0.y * 0.70710678f));
                v1.x = 0.5f * v1.x * (1.0f + erff(v1.x * 0.70710678f));
                v1.y = 0.5f * v1.y * (1.0f + erff(v1.y * 0.70710678f));
            }
            size_t i0 = (size_t)r * N + c;
            size_t i1 = (size_t)(r + 8) * N + c;
            if (OUTH) {
                *(uint32_t*)(Ch + i0) = pack2h(v0.x, v0.y);
                *(uint32_t*)(Ch + i1) = pack2h(v1.x, v1.y);
            } else {
                if (RES) {
                    float2 hp0 = *(const float2*)(hsrc + i0);
                    float2 hp1 = *(const float2*)(hsrc + i1);
                    float w0 = snw[cl], w1 = snw[cl + 1];
                    float c0 = snb[cl], c1 = snb[cl + 1];
                    v0.x += (hp0.x - st0.x) * st0.y * w0 + c0;
                    v0.y += (hp0.y - st0.x) * st0.y * w1 + c1;
                    v1.x += (hp1.x - st1.x) * st1.y * w0 + c0;
                    v1.y += (hp1.y - st1.x) * st1.y * w1 + c1;
                }
                *(float2*)(Cf + i0) = v0;
                *(float2*)(Cf + i1) = v1;
            }
        }
    }
}

// ---------------- embedding + positional encoding ---------------------------
__global__ __launch_bounds__(256) void embed_kernel(
    const int* __restrict__ x, const float* __restrict__ ew,
    float* __restrict__ h)
{
    int row = blockIdx.x;
    int d   = threadIdx.x;
    int s   = row & (S_ - 1);
    int tok = x[row];
    int p   = d >> 1;
    float dim_t = powf(10000.0f, (float)p * (1.0f / 128.0f));
    float pos   = (float)s / dim_t;
    float pe    = (d & 1) ? cosf(pos) : sinf(pos);
    h[(size_t)row * D_ + d] = ew[(size_t)tok * D_ + d] + pe;
}

// ---------------- LayerNorm -> fp16 + per-row stats --------------------------
__global__ __launch_bounds__(256) void ln_kernel(
    const float* __restrict__ in, __half* __restrict__ outH,
    float* __restrict__ stats,
    const float* __restrict__ w, const float* __restrict__ b)
{
    int warp = threadIdx.x >> 5, lane = threadIdx.x & 31;
    size_t row = (size_t)blockIdx.x * 8 + warp;
    const float* p = in + row * D_;
    float4 a0 = *(const float4*)(p + lane * 4);
    float4 a1 = *(const float4*)(p + 128 + lane * 4);
    float s = a0.x + a0.y + a0.z + a0.w + a1.x + a1.y + a1.z + a1.w;
    float q = a0.x*a0.x + a0.y*a0.y + a0.z*a0.z + a0.w*a0.w
            + a1.x*a1.x + a1.y*a1.y + a1.z*a1.z + a1.w*a1.w;
#pragma unroll
    for (int o = 16; o > 0; o >>= 1) {
        s += __shfl_xor_sync(0xffffffffu, s, o);
        q += __shfl_xor_sync(0xffffffffu, q, o);
    }
    float mean = s * (1.0f / 256.0f);
    float var  = q * (1.0f / 256.0f) - mean * mean;
    float rstd = rsqrtf(var + 1e-5f);
    if (lane == 0) {
        *(float2*)(stats + 2 * row) = make_float2(mean, rstd);
    }
    float4 w0 = *(const float4*)(w + lane * 4);
    float4 w1 = *(const float4*)(w + 128 + lane * 4);
    float4 b0 = *(const float4*)(b + lane * 4);
    float4 b1 = *(const float4*)(b + 128 + lane * 4);
    float4 o0, o1;
    o0.x = (a0.x - mean) * rstd * w0.x + b0.x;
    o0.y = (a0.y - mean) * rstd * w0.y + b0.y;
    o0.z = (a0.z - mean) * rstd * w0.z + b0.z;
    o0.w = (a0.w - mean) * rstd * w0.w + b0.w;
    o1.x = (a1.x - mean) * rstd * w1.x + b1.x;
    o1.y = (a1.y - mean) * rstd * w1.y + b1.y;
    o1.z = (a1.z - mean) * rstd * w1.z + b1.z;
    o1.w = (a1.w - mean) * rstd * w1.w + b1.w;
    *(uint2*)(outH + row * D_ + lane * 4) =
        make_uint2(pack2h(o0.x, o0.y), pack2h(o0.z, o0.w));
    *(uint2*)(outH + row * D_ + 128 + lane * 4) =
        make_uint2(pack2h(o1.x, o1.y), pack2h(o1.z, o1.w));
}

// ---------------- attention: tensor-core FA (mma QK + PV) --------------------
#define ATTN_SMEM (3 * 16384 + 512)   // 49664

__global__ __launch_bounds__(256) void attn_kernel(
    const __half* __restrict__ qkv, const float* __restrict__ ids,
    __half* __restrict__ oh)
{
    char* smem = dyn_smem;
    const uint32_t sb = smem_u32(smem);
    const uint32_t sQ = sb;
    const uint32_t sK = sb + 16384;
    const uint32_t sV = sb + 32768;
    float* msk = (float*)(smem + 49152);
    const int h = blockIdx.x, b = blockIdx.y, t = threadIdx.x;
    const int lane = t & 31, warp = t >> 5;
    const __half* base = qkv + (size_t)b * S_ * 768 + h * DH_;

    for (int idx = t; idx < 1024; idx += 256) {
        int r = idx >> 3, g = idx & 7;
        uint32_t off = (uint32_t)(r * 128 + ((g ^ (r & 7)) << 4));
        const __half* src = base + (size_t)r * 768 + g * 8;
        *(uint4*)(smem + off)         = *(const uint4*)(src);
        *(uint4*)(smem + 16384 + off) = *(const uint4*)(src + 256);
        *(uint4*)(smem + 32768 + off) = *(const uint4*)(src + 512);
    }
    if (t < 128) msk[t] = ids[b * S_ + t] * (-1e9f * SCALE_ * LOG2E_);
    __syncthreads();

    float sacc[16][4];
#pragma unroll
    for (int nt = 0; nt < 16; nt++)
#pragma unroll
        for (int k = 0; k < 4; k++) sacc[nt][k] = 0.0f;

    const int mrow0 = warp * 16;
#pragma unroll
    for (int ks = 0; ks < 4; ks++) {
        uint32_t a[4];
        {
            int row = mrow0 + (lane & 15);
            int cg  = ks * 2 + (lane >> 4);
            ldsm4(sQ + row * 128 + ((cg ^ (row & 7)) << 4), a);
        }
#pragma unroll
        for (int nt = 0; nt < 16; nt++) {
            uint32_t bf[2];
            int row = nt * 8 + (lane & 7);
            int cg  = ks * 2 + ((lane >> 3) & 1);
            ldsm2(sK + row * 128 + ((cg ^ (row & 7)) << 4), bf);
            mma16816h(sacc[nt], a, bf);
        }
    }

    const float kscale = SCALE_ * LOG2E_;
    float m0 = -1e30f, m1 = -1e30f;
    const int cq = (lane & 3) * 2;
#pragma unroll
    for (int nt = 0; nt < 16; nt++) {
        float2 mk = *(float2*)(msk + nt * 8 + cq);
        sacc[nt][0] = fmaf(sacc[nt][0], kscale, mk.x);
        sacc[nt][1] = fmaf(sacc[nt][1], kscale, mk.y);
        sacc[nt][2] = fmaf(sacc[nt][2], kscale, mk.x);
        sacc[nt][3] = fmaf(sacc[nt][3], kscale, mk.y);
        m0 = fmaxf(m0, fmaxf(sacc[nt][0], sacc[nt][1]));
        m1 = fmaxf(m1, fmaxf(sacc[nt][2], sacc[nt][3]));
    }
    m0 = fmaxf(m0, __shfl_xor_sync(0xffffffffu, m0, 1));
    m0 = fmaxf(m0, __shfl_xor_sync(0xffffffffu, m0, 2));
    m1 = fmaxf(m1, __shfl_xor_sync(0xffffffffu, m1, 1));
    m1 = fmaxf(m1, __shfl_xor_sync(0xffffffffu, m1, 2));

    float l0 = 0.0f, l1 = 0.0f;
    uint32_t pa[16], pb[16];
#pragma unroll
    for (int nt = 0; nt < 16; nt++) {
        __half2 d0 = __floats2half2_rn(sacc[nt][0] - m0, sacc[nt][1] - m0);
        __half2 p0 = h2exp2(d0);
        float2 f0 = __half22float2(p0);
        l0 += f0.x + f0.y;
        memcpy(&pa[nt], &p0, 4);
        __half2 d1 = __floats2half2_rn(sacc[nt][2] - m1, sacc[nt][3] - m1);
        __half2 p1 = h2exp2(d1);
        float2 f1 = __half22float2(p1);
        l1 += f1.x + f1.y;
        memcpy(&pb[nt], &p1, 4);
    }
    l0 += __shfl_xor_sync(0xffffffffu, l0, 1);
    l0 += __shfl_xor_sync(0xffffffffu, l0, 2);
    l1 += __shfl_xor_sync(0xffffffffu, l1, 1);
    l1 += __shfl_xor_sync(0xffffffffu, l1, 2);
    float inv0 = 1.0f / l0, inv1 = 1.0f / l1;

    float oacc[8][4];
#pragma unroll
    for (int vt = 0; vt < 8; vt++)
#pragma unroll
        for (int k = 0; k < 4; k++) oacc[vt][k] = 0.0f;

#pragma unroll
    for (int kk = 0; kk < 8; kk++) {
        uint32_t a[4] = {pa[2 * kk], pb[2 * kk], pa[2 * kk + 1], pb[2 * kk + 1]};
        int row = kk * 16 + (lane & 15);
        uint32_t rbase = sV + row * 128;
        uint32_t rsw = (row & 7) << 4;
#pragma unroll
        for (int vt = 0; vt < 8; vt++) {
            uint32_t bf[2];
            ldsm2t(rbase + (((uint32_t)vt << 4) ^ rsw), bf);
            mma16816h(oacc[vt], a, bf);
        }
    }

    size_t rbase = (size_t)(b * S_ + mrow0 + (lane >> 2)) * D_ + h * DH_;
#pragma unroll
    for (int vt = 0; vt < 8; vt++) {
        int col = vt * 8 + cq;
        *(uint32_t*)(oh + rbase + col) =
            pack2h(oacc[vt][0] * inv0, oacc[vt][1] * inv0);
        *(uint32_t*)(oh + rbase + (size_t)8 * D_ + col) =
            pack2h(oacc[vt][2] * inv1, oacc[vt][3] * inv1);
    }
}

// ---------------- final logits ---------------------------------------------
__global__ __launch_bounds__(256) void logits_kernel(
    const float* __restrict__ hflat, const float* __restrict__ W,
    const float* __restrict__ bias, float* __restrict__ out)
{
    int b = blockIdx.x, t = threadIdx.x;
    const float4* h4  = (const float4*)(hflat + (size_t)b * 32768);
    const float4* w04 = (const float4*)(W);
    const float4* w14 = (const float4*)(W + 32768);
    float a0 = 0.0f, a1 = 0.0f;
    for (int i = t; i < 8192; i += 256) {
        float4 x = h4[i], u = w04[i], v = w14[i];
        a0 += x.x*u.x + x.y*u.y + x.z*u.z + x.w*u.w;
        a1 += x.x*v.x + x.y*v.y + x.z*v.z + x.w*v.w;
    }
    __shared__ float r0[256], r1[256];
    r0[t] = a0; r1[t] = a1;
    __syncthreads();
    for (int s = 128; s > 0; s >>= 1) {
        if (t < s) { r0[t] += r0[t + s]; r1[t] += r1[t + s]; }
        __syncthreads();
    }
    if (t == 0) {
        out[b * 2 + 0] = r0[0] + bias[0];
        out[b * 2 + 1] = r1[0] + bias[1];
    }
}

// ---------------- launch ----------------------------------------------------
extern "C" void kernel_launch(void* const* d_in, const int* in_sizes, int n_in,
                              void* d_out, int out_size)
{
    const int*   x    = (const int*)  d_in[0];
    const float* ids  = (const float*)d_in[1];
    const float* ew   = (const float*)d_in[2];
    const float* n1w  = (const float*)d_in[3];
    const float* n1b  = (const float*)d_in[4];
    const float* piw  = (const float*)d_in[5];
    const float* pow_ = (const float*)d_in[6];
    const float* pob  = (const float*)d_in[7];
    const float* n2w  = (const float*)d_in[8];
    const float* n2b  = (const float*)d_in[9];
    const float* l1w  = (const float*)d_in[10];
    const float* l1b  = (const float*)d_in[11];
    const float* l2w  = (const float*)d_in[12];
    const float* l2b  = (const float*)d_in[13];
    const float* lw   = (const float*)d_in[14];
    const float* lb   = (const float*)d_in[15];
    float* out = (float*)d_out;

    float *h, *stats;
    __half *qkvh, *hnH, *tmpH, *wH;
    cudaGetSymbolAddress((void**)&h,     g_h);
    cudaGetSymbolAddress((void**)&stats, g_stats);
    cudaGetSymbolAddress((void**)&qkvh,  g_qkvH);
    cudaGetSymbolAddress((void**)&hnH,   g_hnH);
    cudaGetSymbolAddress((void**)&tmpH,  g_tmpH);
    cudaGetSymbolAddress((void**)&wH,    g_wH);

    cudaFuncSetAttribute(attn_kernel,
                         cudaFuncAttributeMaxDynamicSharedMemorySize, ATTN_SMEM);
    cudaFuncSetAttribute(mgemm_kernel<false,false,false,true>,
                         cudaFuncAttributeMaxDynamicSharedMemorySize, G_SMEM);
    cudaFuncSetAttribute(mgemm_kernel<false,true,true,false>,
                         cudaFuncAttributeMaxDynamicSharedMemorySize, G_SMEM);
    cudaFuncSetAttribute(mgemm_kernel<true,false,true,true>,
                         cudaFuncAttributeMaxDynamicSharedMemorySize, G_SMEM);

    // preconvert all weights to fp16 (once per launch)
    wconv_kernel<<<(L_ * D3D_ / 8 + 255) / 256, 256>>>(piw,  wH + OFF_PIW, L_ * D3D_ / 8);
    wconv_kernel<<<(L_ * DD_  / 8 + 255) / 256, 256>>>(pow_, wH + OFF_POW, L_ * DD_ / 8);
    wconv_kernel<<<(L_ * FFD_ / 8 + 255) / 256, 256>>>(l1w,  wH + OFF_L1W, L_ * FFD_ / 8);
    wconv_kernel<<<(L_ * DFF_ / 8 + 255) / 256, 256>>>(l2w,  wH + OFF_L2W, L_ * DFF_ / 8);

    embed_kernel<<<ROWS_, 256>>>(x, ew, h);

    for (int l = 0; l < L_; l++) {
        ln_kernel<<<ROWS_ / 8, 256>>>(h, hnH, stats, n1w + l * D_, n1b + l * D_);
        // qkv (fp16 out)
        mgemm_kernel<false,false,false,true><<<dim3(6, 512), 256, G_SMEM>>>(
            hnH, wH + OFF_PIW + (size_t)l * D3D_,
            nullptr, nullptr, nullptr, nullptr, nullptr,
            nullptr, qkvh, ROWS_, 3 * D_, D_);
        attn_kernel<<<dim3(H_, B_), 256, ATTN_SMEM>>>(qkvh, ids, tmpH);
        // h = attn_out @ Wo^T + bo + LN1(h)  (residual recomputed from h+stats)
        mgemm_kernel<false,true,true,false><<<dim3(2, 512), 256, G_SMEM>>>(
            tmpH, wH + OFF_POW + (size_t)l * DD_,
            pob + l * D_, h, stats, n1w + l * D_, n1b + l * D_,
            h, nullptr, ROWS_, D_, D_);
        ln_kernel<<<ROWS_ / 8, 256>>>(h, hnH, stats, n2w + l * D_, n2b + l * D_);
        mgemm_kernel<true,false,true,true><<<dim3(3, 512), 256, G_SMEM>>>(
            hnH, wH + OFF_L1W + (size_t)l * FFD_,
            l1b + l * FF_, nullptr, nullptr, nullptr, nullptr,
            nullptr, tmpH, ROWS_, FF_, D_);
        mgemm_kernel<false,true,true,false><<<dim3(2, 512), 256, G_SMEM>>>(
            tmpH, wH + OFF_L2W + (size_t)l * DFF_,
            l2b + l * D_, h, stats, n2w + l * D_, n2b + l * D_,
            h, nullptr, ROWS_, D_, FF_);
    }

    logits_kernel<<<B_, 256>>>(h, lw, lb, out);
}